// round 1
// baseline (speedup 1.0000x reference)
#include <cuda_runtime.h>
#include <math.h>

#define B   128
#define T   256
#define DIN 512
#define H   1024
#define S   128
#define DH  1024

// ---- scratch (device globals; no allocations allowed) ----
__device__ float  g_h[2][B * H];              // double-buffered hidden state
__device__ float  g_c[B * H];                 // cell state (elementwise-owned, safe in place)
__device__ float  g_z[(T + 1) * B * S];       // z slots: slot 0 = zeros, slot t+1 = z after step t
__device__ float  g_hid[(size_t)B * T * DH];  // decoder intermediate (134 MB)
__device__ double g_klpart[T * 128];          // deterministic KL partials

__device__ __forceinline__ float sigf(float x) { return 1.0f / (1.0f + expf(-x)); }

// ---------------------------------------------------------------------------
// init: zero recurrent state each replay (graph is re-run; state must reset)
// ---------------------------------------------------------------------------
__global__ void init_kernel() {
    int stride = gridDim.x * blockDim.x;
    int tid0 = blockIdx.x * blockDim.x + threadIdx.x;
    float* hb = (float*)g_h;
    for (int i = tid0; i < 2 * B * H; i += stride) hb[i] = 0.0f;
    for (int i = tid0; i < B * H; i += stride) g_c[i] = 0.0f;
    for (int i = tid0; i < B * S; i += stride) g_z[i] = 0.0f;
}

// ---------------------------------------------------------------------------
// K1: gates = z_prev@W_ih^T + h@W_hh^T + b  (gate-interleaved tiles), fused LSTM
// grid: 128 CTAs (each owns 8 hidden units x 4 gates = 32 output cols, M=128)
// ---------------------------------------------------------------------------
__global__ __launch_bounds__(256) void lstm_kernel(
    const float* __restrict__ zprev, const float* __restrict__ hin,
    float* __restrict__ hout,
    const float* __restrict__ Wih, const float* __restrict__ Whh,
    const float* __restrict__ bih, const float* __restrict__ bhh)
{
    __shared__ float As[32][128];   // A tile, transposed: As[k][b]
    __shared__ float Ws[32][32];    // W tile, swizzled groups of 4 gates

    const int tid = threadIdx.x;
    const int tx = tid & 7;          // hidden unit within tile (jj)
    const int ty = tid >> 3;         // batch group (4 rows each)
    const int hbase = blockIdx.x * 8;

    float acc[4][4];
    #pragma unroll
    for (int g = 0; g < 4; g++)
        #pragma unroll
        for (int b2 = 0; b2 < 4; b2++) acc[g][b2] = 0.0f;

    // W loader mapping (fixed per thread)
    const int cw = tid >> 3;            // 0..31 column id
    const int g_w = cw & 3;             // gate
    const int jj_w = cw >> 2;           // hidden unit in tile
    const int klw = (tid & 7) * 4;      // k within block
    const int wrow = g_w * H + hbase + jj_w;
    const int colg = (jj_w ^ (klw >> 2)) * 4 + g_w;   // XOR swizzle (conflict-free)

    #pragma unroll
    for (int phase = 0; phase < 2; phase++) {
        const float* A = phase ? hin : zprev;
        const float* W = phase ? Whh : Wih;
        const int K = phase ? H : S;
        for (int k0 = 0; k0 < K; k0 += 32) {
            #pragma unroll
            for (int i = 0; i < 4; i++) {
                int idx = tid + i * 256;
                int bb = idx & 127, kg = idx >> 7;
                float4 v = *(const float4*)(A + (size_t)bb * K + k0 + kg * 4);
                As[kg * 4 + 0][bb] = v.x; As[kg * 4 + 1][bb] = v.y;
                As[kg * 4 + 2][bb] = v.z; As[kg * 4 + 3][bb] = v.w;
            }
            {
                float4 v = *(const float4*)(W + (size_t)wrow * K + k0 + klw);
                Ws[klw + 0][colg] = v.x; Ws[klw + 1][colg] = v.y;
                Ws[klw + 2][colg] = v.z; Ws[klw + 3][colg] = v.w;
            }
            __syncthreads();
            #pragma unroll
            for (int k = 0; k < 32; k++) {
                float4 a = *(const float4*)&As[k][ty * 4];
                float4 w = *(const float4*)&Ws[k][(tx ^ (k >> 2)) * 4];
                float av[4] = {a.x, a.y, a.z, a.w};
                float wv[4] = {w.x, w.y, w.z, w.w};
                #pragma unroll
                for (int g = 0; g < 4; g++)
                    #pragma unroll
                    for (int b2 = 0; b2 < 4; b2++)
                        acc[g][b2] = fmaf(wv[g], av[b2], acc[g][b2]);
            }
            __syncthreads();
        }
    }

    // fused LSTM pointwise: this thread owns hidden unit j for 4 batch rows
    const int j = hbase + tx;
    const float bI = bih[j] + bhh[j];
    const float bF = bih[H + j] + bhh[H + j];
    const float bG = bih[2 * H + j] + bhh[2 * H + j];
    const float bO = bih[3 * H + j] + bhh[3 * H + j];
    #pragma unroll
    for (int b2 = 0; b2 < 4; b2++) {
        int b = ty * 4 + b2;
        float ig = sigf(acc[0][b2] + bI);
        float fg = sigf(acc[1][b2] + bF);
        float gg = tanhf(acc[2][b2] + bG);
        float og = sigf(acc[3][b2] + bO);
        float cn = fg * g_c[b * H + j] + ig * gg;
        g_c[b * H + j] = cn;
        hout[b * H + j] = og * tanhf(cn);
    }
}

// ---------------------------------------------------------------------------
// K2: posterior heads + reparam + KL partial.
// grid: 128 CTAs = 64 s-pairs x 2 batch halves; thread = one (b, s, mean|lv)
// ---------------------------------------------------------------------------
__global__ __launch_bounds__(256) void post_kernel(
    const float* __restrict__ x, const float* __restrict__ noise,
    const float* __restrict__ h, float* __restrict__ zout,
    const float* __restrict__ Wm, const float* __restrict__ bm,
    const float* __restrict__ Wv, const float* __restrict__ bv, int t)
{
    __shared__ float Wrows[4][DIN + H];  // 4 rows (2 s x {Wm,Wv}) staged
    __shared__ float vals[256];
    __shared__ double klred[8];

    const int tid = threadIdx.x;
    const int bx = blockIdx.x;
    const int sgrp = bx >> 1, bgrp = bx & 1;

    #pragma unroll
    for (int i = 0; i < 6; i++) {
        int idx = tid + i * 256;        // 1536 float4 ids total
        int r = idx / 384;
        int k4 = idx - r * 384;
        const float* src = (r & 1) ? Wv : Wm;
        int srow = sgrp * 2 + (r >> 1);
        *(float4*)&Wrows[r][k4 * 4] =
            *(const float4*)(src + (size_t)srow * (DIN + H) + k4 * 4);
    }
    __syncthreads();

    const int b_l = tid >> 2, s_l = (tid >> 1) & 1, which = tid & 1;
    const int b = bgrp * 64 + b_l, s = sgrp * 2 + s_l;
    const float* Wr = Wrows[s_l * 2 + which];
    const float* px = x + (size_t)b * T * DIN + (size_t)t * DIN;
    const float* ph = h + (size_t)b * H;

    float acc = which ? bv[s] : bm[s];
    #pragma unroll 4
    for (int k4 = 0; k4 < DIN / 4; k4++) {
        float4 p = *(const float4*)(px + k4 * 4);
        float4 w = *(const float4*)(Wr + k4 * 4);
        acc = fmaf(p.x, w.x, acc); acc = fmaf(p.y, w.y, acc);
        acc = fmaf(p.z, w.z, acc); acc = fmaf(p.w, w.w, acc);
    }
    #pragma unroll 4
    for (int k4 = 0; k4 < H / 4; k4++) {
        float4 p = *(const float4*)(ph + k4 * 4);
        float4 w = *(const float4*)(Wr + DIN + k4 * 4);
        acc = fmaf(p.x, w.x, acc); acc = fmaf(p.y, w.y, acc);
        acc = fmaf(p.z, w.z, acc); acc = fmaf(p.w, w.w, acc);
    }
    vals[tid] = acc;
    __syncthreads();

    float klterm = 0.0f;
    if (which == 0) {
        float mean = acc, lv = vals[tid | 1];
        float sd = expf(0.5f * lv);
        float nt = noise[(size_t)b * T * S + (size_t)t * S + s];
        zout[b * S + s] = nt * sd + mean;
        klterm = expf(lv) + mean * mean - 0.5f * lv - 0.5f;
    }
    #pragma unroll
    for (int off = 16; off; off >>= 1)
        klterm += __shfl_down_sync(0xffffffffu, klterm, off);
    if ((tid & 31) == 0) klred[tid >> 5] = (double)klterm;
    __syncthreads();
    if (tid == 0) {
        double ssum = 0.0;
        #pragma unroll
        for (int w = 0; w < 8; w++) ssum += klred[w];
        g_klpart[t * 128 + bx] = ssum;
    }
}

// ---------------------------------------------------------------------------
// Decoder GEMM1: hid = relu(Z @ Wd1^T + bd1), Z rows = g_z slots 1..T
// grid: (16 n-tiles of 64, 256 row-tiles of 128)
// ---------------------------------------------------------------------------
__global__ __launch_bounds__(256) void dec_gemm1(
    const float* __restrict__ Wd1, const float* __restrict__ bd1)
{
    __shared__ float As[32][128];
    __shared__ float Ws[32][64];
    const int tid = threadIdx.x;
    const int tx = tid & 15, ty = tid >> 4;
    const int nb = blockIdx.x * 64;
    const int rb = blockIdx.y * 128;
    const float* A = g_z + B * S + (size_t)rb * S;   // ld = 128

    float acc[8][4];
    #pragma unroll
    for (int r = 0; r < 8; r++)
        #pragma unroll
        for (int c = 0; c < 4; c++) acc[r][c] = 0.0f;

    for (int k0 = 0; k0 < S; k0 += 32) {
        #pragma unroll
        for (int i = 0; i < 4; i++) {
            int idx = tid + i * 256;
            int rr = idx & 127, kg = idx >> 7;
            float4 v = *(const float4*)(A + (size_t)rr * S + k0 + kg * 4);
            As[kg * 4 + 0][rr] = v.x; As[kg * 4 + 1][rr] = v.y;
            As[kg * 4 + 2][rr] = v.z; As[kg * 4 + 3][rr] = v.w;
        }
        #pragma unroll
        for (int i = 0; i < 2; i++) {
            int idx = tid + i * 256;
            int k4 = idx & 7, n_l = idx >> 3;
            float4 v = *(const float4*)(Wd1 + (size_t)(nb + n_l) * S + k0 + k4 * 4);
            int cg = (((n_l >> 2) ^ k4)) * 4 + (n_l & 3);
            Ws[k4 * 4 + 0][cg] = v.x; Ws[k4 * 4 + 1][cg] = v.y;
            Ws[k4 * 4 + 2][cg] = v.z; Ws[k4 * 4 + 3][cg] = v.w;
        }
        __syncthreads();
        #pragma unroll
        for (int k = 0; k < 32; k++) {
            float4 a0 = *(const float4*)&As[k][ty * 8];
            float4 a1 = *(const float4*)&As[k][ty * 8 + 4];
            float4 w  = *(const float4*)&Ws[k][(tx ^ (k >> 2)) * 4];
            float av[8] = {a0.x, a0.y, a0.z, a0.w, a1.x, a1.y, a1.z, a1.w};
            float wv[4] = {w.x, w.y, w.z, w.w};
            #pragma unroll
            for (int r = 0; r < 8; r++)
                #pragma unroll
                for (int c = 0; c < 4; c++)
                    acc[r][c] = fmaf(av[r], wv[c], acc[r][c]);
        }
        __syncthreads();
    }
    #pragma unroll
    for (int r = 0; r < 8; r++) {
        int row = rb + ty * 8 + r;
        int n0 = nb + tx * 4;
        float4 o;
        o.x = fmaxf(acc[r][0] + bd1[n0 + 0], 0.0f);
        o.y = fmaxf(acc[r][1] + bd1[n0 + 1], 0.0f);
        o.z = fmaxf(acc[r][2] + bd1[n0 + 2], 0.0f);
        o.w = fmaxf(acc[r][3] + bd1[n0 + 3], 0.0f);
        *(float4*)&g_hid[(size_t)row * DH + n0] = o;
    }
}

// ---------------------------------------------------------------------------
// Decoder GEMM2: x_hat = hid @ Wd2^T + bd2 -> d_out [B,T,DIN]
// grid: (8 n-tiles of 64, 256 row-tiles of 128)
// ---------------------------------------------------------------------------
__global__ __launch_bounds__(256) void dec_gemm2(
    const float* __restrict__ Wd2, const float* __restrict__ bd2,
    float* __restrict__ out)
{
    __shared__ float As[32][128];
    __shared__ float Ws[32][64];
    const int tid = threadIdx.x;
    const int tx = tid & 15, ty = tid >> 4;
    const int nb = blockIdx.x * 64;
    const int rb = blockIdx.y * 128;
    const float* A = g_hid + (size_t)rb * DH;   // ld = 1024

    float acc[8][4];
    #pragma unroll
    for (int r = 0; r < 8; r++)
        #pragma unroll
        for (int c = 0; c < 4; c++) acc[r][c] = 0.0f;

    for (int k0 = 0; k0 < DH; k0 += 32) {
        #pragma unroll
        for (int i = 0; i < 4; i++) {
            int idx = tid + i * 256;
            int rr = idx & 127, kg = idx >> 7;
            float4 v = *(const float4*)(A + (size_t)rr * DH + k0 + kg * 4);
            As[kg * 4 + 0][rr] = v.x; As[kg * 4 + 1][rr] = v.y;
            As[kg * 4 + 2][rr] = v.z; As[kg * 4 + 3][rr] = v.w;
        }
        #pragma unroll
        for (int i = 0; i < 2; i++) {
            int idx = tid + i * 256;
            int k4 = idx & 7, n_l = idx >> 3;
            float4 v = *(const float4*)(Wd2 + (size_t)(nb + n_l) * DH + k0 + k4 * 4);
            int cg = (((n_l >> 2) ^ k4)) * 4 + (n_l & 3);
            Ws[k4 * 4 + 0][cg] = v.x; Ws[k4 * 4 + 1][cg] = v.y;
            Ws[k4 * 4 + 2][cg] = v.z; Ws[k4 * 4 + 3][cg] = v.w;
        }
        __syncthreads();
        #pragma unroll
        for (int k = 0; k < 32; k++) {
            float4 a0 = *(const float4*)&As[k][ty * 8];
            float4 a1 = *(const float4*)&As[k][ty * 8 + 4];
            float4 w  = *(const float4*)&Ws[k][(tx ^ (k >> 2)) * 4];
            float av[8] = {a0.x, a0.y, a0.z, a0.w, a1.x, a1.y, a1.z, a1.w};
            float wv[4] = {w.x, w.y, w.z, w.w};
            #pragma unroll
            for (int r = 0; r < 8; r++)
                #pragma unroll
                for (int c = 0; c < 4; c++)
                    acc[r][c] = fmaf(av[r], wv[c], acc[r][c]);
        }
        __syncthreads();
    }
    #pragma unroll
    for (int r = 0; r < 8; r++) {
        int row = rb + ty * 8 + r;       // row = t*128 + b
        int tt = row >> 7, bb = row & 127;
        int n0 = nb + tx * 4;
        float4 o;
        o.x = acc[r][0] + bd2[n0 + 0];
        o.y = acc[r][1] + bd2[n0 + 1];
        o.z = acc[r][2] + bd2[n0 + 2];
        o.w = acc[r][3] + bd2[n0 + 3];
        *(float4*)&out[(size_t)bb * T * DIN + (size_t)tt * DIN + n0] = o;
    }
}

// ---------------------------------------------------------------------------
// Final KL reduction (deterministic, fixed order)
// ---------------------------------------------------------------------------
__global__ void kl_kernel(float* __restrict__ out) {
    __shared__ double red[256];
    int tid = threadIdx.x;
    double ssum = 0.0;
    for (int i = tid; i < T * 128; i += 256) ssum += g_klpart[i];
    red[tid] = ssum;
    __syncthreads();
    for (int off = 128; off; off >>= 1) {
        if (tid < off) red[tid] += red[tid + off];
        __syncthreads();
    }
    if (tid == 0) out[(size_t)B * T * DIN] = (float)red[0];
}

// ---------------------------------------------------------------------------
extern "C" void kernel_launch(void* const* d_in, const int* in_sizes, int n_in,
                              void* d_out, int out_size)
{
    const float* x     = (const float*)d_in[0];
    const float* noise = (const float*)d_in[1];
    const float* Wih   = (const float*)d_in[2];
    const float* Whh   = (const float*)d_in[3];
    const float* bih   = (const float*)d_in[4];
    const float* bhh   = (const float*)d_in[5];
    const float* Wm    = (const float*)d_in[6];
    const float* bm    = (const float*)d_in[7];
    const float* Wv    = (const float*)d_in[8];
    const float* bv    = (const float*)d_in[9];
    const float* Wd1   = (const float*)d_in[10];
    const float* bd1   = (const float*)d_in[11];
    const float* Wd2   = (const float*)d_in[12];
    const float* bd2   = (const float*)d_in[13];
    float* out = (float*)d_out;

    float *p_z, *p_h;
    cudaGetSymbolAddress((void**)&p_z, g_z);
    cudaGetSymbolAddress((void**)&p_h, g_h);

    init_kernel<<<256, 256>>>();

    for (int t = 0; t < T; t++) {
        lstm_kernel<<<128, 256>>>(p_z + (size_t)t * B * S,
                                  p_h + (size_t)(t & 1) * B * H,
                                  p_h + (size_t)((t + 1) & 1) * B * H,
                                  Wih, Whh, bih, bhh);
        post_kernel<<<128, 256>>>(x, noise,
                                  p_h + (size_t)((t + 1) & 1) * B * H,
                                  p_z + (size_t)(t + 1) * B * S,
                                  Wm, bm, Wv, bv, t);
    }
    dec_gemm1<<<dim3(16, 256), 256>>>(Wd1, bd1);
    dec_gemm2<<<dim3(8, 256), 256>>>(Wd2, bd2, out);
    kl_kernel<<<1, 256>>>(out);
}